// round 11
// baseline (speedup 1.0000x reference)
#include <cuda_runtime.h>
#include <stdint.h>

// out[i, 0:8] = params[idx[i]] * xs[i, 0:8]
// xs: float32 [N, 8]; idx: int32 [N]; params: float32 [V]; out: float32 [N, 8]
// N = 4194304, V = 1048576.
//
// Final structure (measured best across 8 variants): direct LDG/STG,
// 2 threads per row -> every streaming access is a dense 16B lane-contiguous
// wavefront; lane pairs broadcast the idx/param access. Streams are
// evict-first (__ldcs/__stcs); the param gather bypasses L1 and is pinned
// evict_last in L2 via a createpolicy cache-hint (scalar ld can't take the
// direct .L2::evict_last qualifier on sm_103). TMA/smem staging regressed
// (R7/R8): zero-reuse streams belong on the LDG/STG path.

#define N_ROWS  4194304
#define ITEMS   (2 * N_ROWS)                   // 8M float4 half-rows
#define UNROLL  4
#define THREADS 256
#define BLOCKS  (ITEMS / (UNROLL * THREADS))   // 8192

__device__ __forceinline__ uint64_t make_evict_last_policy() {
    uint64_t pol;
    asm volatile("createpolicy.fractional.L2::evict_last.b64 %0, 1.0;"
                 : "=l"(pol));
    return pol;
}

__device__ __forceinline__ float ldg_l2_pinned(const float* p, uint64_t pol) {
    float v;
    asm volatile("ld.global.nc.L2::cache_hint.f32 %0, [%1], %2;"
                 : "=f"(v) : "l"(p), "l"(pol));
    return v;
}

__global__ __launch_bounds__(THREADS) void gather_mul_kernel(
    const float4* __restrict__ xs,     // [ITEMS]
    const int*    __restrict__ idx,    // [N] int32
    const float*  __restrict__ params, // [V]
    float4*       __restrict__ out)    // [ITEMS]
{
    const int t = blockIdx.x * THREADS + threadIdx.x;
    const int S = BLOCKS * THREADS;    // 2M items per sweep

    const uint64_t pol = make_evict_last_policy();

    // 1) Batch index loads (lane pairs share an address -> broadcast).
    int j[UNROLL];
#pragma unroll
    for (int k = 0; k < UNROLL; k++)
        j[k] = __ldcs(idx + ((t + k * S) >> 1));

    // 2) Batch param gathers: L1-bypass, L2 evict_last (table stays pinned).
    float p[UNROLL];
#pragma unroll
    for (int k = 0; k < UNROLL; k++)
        p[k] = ldg_l2_pinned(params + j[k], pol);

    // 3) Batch xs half-row loads: 16B lane-contiguous, evict-first.
    float4 x[UNROLL];
#pragma unroll
    for (int k = 0; k < UNROLL; k++)
        x[k] = __ldcs(xs + t + k * S);

    // 4) Multiply + streaming stores (evict-first).
#pragma unroll
    for (int k = 0; k < UNROLL; k++) {
        float4 o;
        o.x = p[k] * x[k].x;
        o.y = p[k] * x[k].y;
        o.z = p[k] * x[k].z;
        o.w = p[k] * x[k].w;
        __stcs(out + t + k * S, o);
    }
}

extern "C" void kernel_launch(void* const* d_in, const int* in_sizes, int n_in,
                              void* d_out, int out_size)
{
    const float4* xs     = (const float4*)d_in[0];
    const int*    idx    = (const int*)d_in[1];
    const float*  params = (const float*)d_in[2];
    float4*       out    = (float4*)d_out;

    gather_mul_kernel<<<BLOCKS, THREADS>>>(xs, idx, params, out);
}